// round 7
// baseline (speedup 1.0000x reference)
#include <cuda_runtime.h>
#include <math_constants.h>

// Problem constants
#define NB   2
#define LL   2048
#define DD   1024
#define HH   16
#define DH   64
#define NHB  (NB*HH)                  // 32
#define NLD  (NB*LL*DD)               // 4194304
#define PAD  132                      // 128 + 4, k-major smem pitch (float4-aligned)

// logits = energy / sqrt(1024); work in base-2: exp(x/32) = exp2(x * log2(e)/32)
__device__ __constant__ float S2c = 1.44269504088896340736f / 32.0f;

// ---------------- scratch (device globals; no allocations allowed) ----------------
__device__ float g_vp [NLD];   // v  = values @ Wv^T        (n,l,h,d) natural
__device__ float g_kp [NLD];   // k  = keys @ Wk^T
__device__ float g_qp [NLD];   // q  = query @ Wq^T
__device__ float g_ovp[NLD];   // ov = origin_values @ Wv^T
__device__ float g_okp[NLD];   // ok = origin_keys @ Wk^T
__device__ float g_samp  [NHB*LL];   // samp_energy[n,h,l] = q(l)·k(l)
__device__ float g_lse2  [NHB*LL];   // log2( sum_l exp2(logit2) ) per row q
__device__ float g_colsum[NHB*LL];   // sum_{q>l} scores[q,l]
__device__ float g_X  [NLD];         // attention output pre-fc

// ============================================================================
// 1) Projection: out[r, :] = X[r, :] @ W^T  for r in [0, N*L*H), 64x64 weight.
//    Block = 64 rows x 64 cols, 16x16 threads, 4x4 microtile.
// ============================================================================
__global__ void __launch_bounds__(256)
proj_kernel(const float* __restrict__ X, const float* __restrict__ W, int which)
{
    float* dsts[5] = { g_vp, g_kp, g_qp, g_ovp, g_okp };
    float* out = dsts[which];

    __shared__ float XsT[64*68];   // k-major: XsT[i][r]
    __shared__ float WsT[64*68];   // k-major: WsT[i][j] = W[j][i]

    const int tid  = threadIdx.x;
    const int rho0 = blockIdx.x * 64;
    const float* Xb = X + (size_t)rho0 * 64;

#pragma unroll
    for (int t = 0; t < 4; ++t) {
        int fid = tid + t * 256;           // 0..1023 float4s
        int r   = fid >> 4;                // row / weight row j
        int i4  = fid & 15;                // k-group
        float4 v = *reinterpret_cast<const float4*>(Xb + fid * 4);
        float* p = XsT + (i4 * 4) * 68 + r;
        p[0] = v.x; p[68] = v.y; p[136] = v.z; p[204] = v.w;
        float4 w = *reinterpret_cast<const float4*>(W + fid * 4);
        float* pw = WsT + (i4 * 4) * 68 + r;
        pw[0] = w.x; pw[68] = w.y; pw[136] = w.z; pw[204] = w.w;
    }
    __syncthreads();

    const int ty = tid >> 4, tx = tid & 15;
    float acc[4][4] = {};
#pragma unroll 8
    for (int i = 0; i < 64; ++i) {
        float4 a = *reinterpret_cast<const float4*>(XsT + i * 68 + ty * 4);
        float4 b = *reinterpret_cast<const float4*>(WsT + i * 68 + tx * 4);
        float av[4] = {a.x, a.y, a.z, a.w};
        float bv[4] = {b.x, b.y, b.z, b.w};
#pragma unroll
        for (int r = 0; r < 4; ++r)
#pragma unroll
            for (int c = 0; c < 4; ++c)
                acc[r][c] = fmaf(av[r], bv[c], acc[r][c]);
    }
#pragma unroll
    for (int r = 0; r < 4; ++r) {
        float4 o = make_float4(acc[r][0], acc[r][1], acc[r][2], acc[r][3]);
        *reinterpret_cast<float4*>(out + (size_t)(rho0 + ty * 4 + r) * 64 + tx * 4) = o;
    }
}

// ============================================================================
// 2) samp_energy[n,h,l] = dot(q[n,l,h,:], k[n,l,h,:])  — one warp per row
// ============================================================================
__global__ void __launch_bounds__(256)
samp_kernel()
{
    int gw   = blockIdx.x * 8 + (threadIdx.x >> 5);   // (n*L + l)*H + h
    int lane = threadIdx.x & 31;
    int n = gw >> 15;
    int rem = gw & 32767;
    int l = rem >> 4;
    int h = rem & 15;
    size_t base = (size_t)gw * 64;
    float p = g_qp[base + lane]      * g_kp[base + lane]
            + g_qp[base + 32 + lane] * g_kp[base + 32 + lane];
#pragma unroll
    for (int o = 16; o; o >>= 1) p += __shfl_xor_sync(0xffffffffu, p, o);
    if (lane == 0) g_samp[(n * HH + h) * LL + l] = p;
}

// ---------------- shared tile loader: 128 rows x 64 cols -> k-major [64][PAD] ----
__device__ __forceinline__ void
load_tileT(const float* __restrict__ src, size_t base, int r0, float* dstT, int tid)
{
#pragma unroll
    for (int t = 0; t < 8; ++t) {
        int fid = tid + t * 256;          // 0..2047 float4s
        int m   = fid >> 4;               // row in tile 0..127
        int d4  = fid & 15;               // k group 0..15
        const float4 v = *reinterpret_cast<const float4*>(
            src + base + (size_t)(r0 + m) * DD + d4 * 4);
        float* p = dstT + (d4 * 4) * PAD + m;
        p[0] = v.x; p[PAD] = v.y; p[2*PAD] = v.z; p[3*PAD] = v.w;
    }
}

// ---------------- 8x8 microtile energy: acc[i][j] += sum_d aT[d][i8]*bT[d][j8] ----
__device__ __forceinline__ void
mma_tile(float acc[8][8], const float* __restrict__ aT, const float* __restrict__ bT,
         int ty, int tx)
{
#pragma unroll 8
    for (int d = 0; d < 64; ++d) {
        float4 t0 = *reinterpret_cast<const float4*>(aT + d * PAD + ty * 8);
        float4 t1 = *reinterpret_cast<const float4*>(aT + d * PAD + ty * 8 + 4);
        float4 u0 = *reinterpret_cast<const float4*>(bT + d * PAD + tx * 8);
        float4 u1 = *reinterpret_cast<const float4*>(bT + d * PAD + tx * 8 + 4);
        float a[8] = {t0.x, t0.y, t0.z, t0.w, t1.x, t1.y, t1.z, t1.w};
        float b[8] = {u0.x, u0.y, u0.z, u0.w, u1.x, u1.y, u1.z, u1.w};
#pragma unroll
        for (int i = 0; i < 8; ++i)
#pragma unroll
            for (int j = 0; j < 8; ++j)
                acc[i][j] = fmaf(a[i], b[j], acc[i][j]);
    }
}

// ============================================================================
// 3) Pass 1: per-row log2-sum-exp over the causal row (diag replaced by samp).
//    block = (qblk, nh); 128 rows; tiles over columns 0..q0+127.
// ============================================================================
__global__ void __launch_bounds__(256, 2)
pass1_kernel()
{
    extern __shared__ float sm[];
    float* okT   = sm;
    float* qsT   = sm + 64 * PAD;
    float* sampS = sm + 2 * 64 * PAD;   // 128 floats

    const int tid = threadIdx.x;
    const int ty = tid >> 4, tx = tid & 15;
    const int nh = blockIdx.y;
    const int n = nh >> 4, h = nh & 15;
    const int qblk = blockIdx.x;
    const int q0 = qblk * 128;
    const size_t base = (size_t)n * LL * DD + (size_t)h * DH;
    const float S2 = S2c;

    load_tileT(g_qp, base, q0, qsT, tid);
    if (tid < 128) sampS[tid] = g_samp[nh * LL + q0 + tid];

    float srun[8] = {};
    for (int ct = 0; ct <= qblk; ++ct) {
        __syncthreads();
        load_tileT(g_okp, base, ct * 128, okT, tid);
        __syncthreads();

        float acc[8][8] = {};
        mma_tile(acc, qsT, okT, ty, tx);

        const bool dt = (ct == qblk);
#pragma unroll
        for (int i = 0; i < 8; ++i) {
            const int rloc = ty * 8 + i;
#pragma unroll
            for (int j = 0; j < 8; ++j) {
                const int cloc = tx * 8 + j;
                float ev = acc[i][j];
                if (dt) {
                    if (cloc > rloc) continue;        // causal mask (future)
                    if (cloc == rloc) ev = sampS[rloc]; // diagonal replacement
                }
                srun[i] += exp2f(ev * S2);
            }
        }
    }

#pragma unroll
    for (int i = 0; i < 8; ++i) {
        float s = srun[i];
        s += __shfl_xor_sync(0xffffffffu, s, 1);
        s += __shfl_xor_sync(0xffffffffu, s, 2);
        s += __shfl_xor_sync(0xffffffffu, s, 4);
        s += __shfl_xor_sync(0xffffffffu, s, 8);
        if (tx == 0) g_lse2[nh * LL + q0 + ty * 8 + i] = log2f(s);
    }
}

// ============================================================================
// 4) Pass 2: colsum[n,h,l] = sum_{q>l} exp2(e[q,l]*S2 - lse2[q])
//    block = (lblk, nh); 128 columns; tiles over rows q >= l0.
// ============================================================================
__global__ void __launch_bounds__(256, 2)
pass2_kernel()
{
    extern __shared__ float sm[];
    float* okT  = sm;                 // column tile (fixed)
    float* qsT  = sm + 64 * PAD;      // row tile (per iteration)
    float* lseS = sm + 2 * 64 * PAD;  // 128 floats

    const int tid = threadIdx.x;
    const int ty = tid >> 4, tx = tid & 15;
    const int nh = blockIdx.y;
    const int n = nh >> 4, h = nh & 15;
    const int lblk = blockIdx.x;
    const int l0 = lblk * 128;
    const size_t base = (size_t)n * LL * DD + (size_t)h * DH;
    const float S2 = S2c;

    load_tileT(g_okp, base, l0, okT, tid);

    float csum[8] = {};
    for (int qt = lblk; qt < 16; ++qt) {
        __syncthreads();
        load_tileT(g_qp, base, qt * 128, qsT, tid);
        if (tid < 128) lseS[tid] = g_lse2[nh * LL + qt * 128 + tid];
        __syncthreads();

        float acc[8][8] = {};
        mma_tile(acc, qsT, okT, ty, tx);   // rows = q (ty), cols = l (tx)

        const bool dt = (qt == lblk);
#pragma unroll
        for (int i = 0; i < 8; ++i) {
            const int rloc = ty * 8 + i;
            const float ls = lseS[rloc];
#pragma unroll
            for (int j = 0; j < 8; ++j) {
                const int cloc = tx * 8 + j;
                if (!dt || rloc > cloc)               // strictly q > l (no diag)
                    csum[j] += exp2f(acc[i][j] * S2 - ls);
            }
        }
    }

    __syncthreads();
    float* red = qsT;                      // reuse qsT region: [16][PAD]
#pragma unroll
    for (int j = 0; j < 8; ++j) red[ty * PAD + tx * 8 + j] = csum[j];
    __syncthreads();
    if (tid < 128) {
        float s = 0.0f;
#pragma unroll
        for (int t = 0; t < 16; ++t) s += red[t * PAD + tid];
        g_colsum[nh * LL + l0 + tid] = s;
    }
}

// ============================================================================
// 5) Combine: X[n,l,h,:] = diag_score * v + colsum * ov
// ============================================================================
__global__ void __launch_bounds__(256)
combine_kernel()
{
    int idx = blockIdx.x * 256 + threadIdx.x;     // < N*L*D
    int n = idx >> 21;
    int r = idx & 2097151;
    int l = r >> 10;
    int c = r & 1023;
    int h = c >> 6;
    int si = (n * HH + h) * LL + l;
    float dg = exp2f(g_samp[si] * S2c - g_lse2[si]);
    g_X[idx] = dg * g_vp[idx] + g_colsum[si] * g_ovp[idx];
}

// ============================================================================
// 6) FC: out = X @ fc_w^T + fc_b   (4096 x 1024 x 1024, NT SGEMM)
// ============================================================================
__global__ void __launch_bounds__(256, 2)
fc_kernel(const float* __restrict__ W, const float* __restrict__ bias,
          float* __restrict__ out)
{
    __shared__ float As[16 * PAD];
    __shared__ float Bs[16 * PAD];

    const int tid = threadIdx.x;
    const int ty = tid >> 4, tx = tid & 15;
    const int m0 = blockIdx.y * 128;
    const int j0 = blockIdx.x * 128;

    float acc[8][8] = {};
    for (int kc = 0; kc < 1024; kc += 16) {
        __syncthreads();
#pragma unroll
        for (int t = 0; t < 2; ++t) {
            int fid = tid + t * 256;     // 0..511 float4s
            int r = fid >> 2, k4 = fid & 3;
            float4 va = *reinterpret_cast<const float4*>(
                g_X + (size_t)(m0 + r) * 1024 + kc + k4 * 4);
            float* pa = As + (k4 * 4) * PAD + r;
            pa[0] = va.x; pa[PAD] = va.y; pa[2*PAD] = va.z; pa[3*PAD] = va.w;
            float4 vb = *reinterpret_cast<const float4*>(
                W + (size_t)(j0 + r) * 1024 + kc + k4 * 4);
            float* pb = Bs + (k4 * 4) * PAD + r;
            pb[0] = vb.x; pb[PAD] = vb.y; pb[2*PAD] = vb.z; pb[3*PAD] = vb.w;
        }
        __syncthreads();
#pragma unroll
        for (int k = 0; k < 16; ++k) {
            float4 t0 = *reinterpret_cast<const float4*>(As + k * PAD + ty * 8);
            float4 t1 = *reinterpret_cast<const float4*>(As + k * PAD + ty * 8 + 4);
            float4 u0 = *reinterpret_cast<const float4*>(Bs + k * PAD + tx * 8);
            float4 u1 = *reinterpret_cast<const float4*>(Bs + k * PAD + tx * 8 + 4);
            float a[8] = {t0.x, t0.y, t0.z, t0.w, t1.x, t1.y, t1.z, t1.w};
            float b[8] = {u0.x, u0.y, u0.z, u0.w, u1.x, u1.y, u1.z, u1.w};
#pragma unroll
            for (int i = 0; i < 8; ++i)
#pragma unroll
                for (int j = 0; j < 8; ++j)
                    acc[i][j] = fmaf(a[i], b[j], acc[i][j]);
        }
    }

    float4 bb0 = *reinterpret_cast<const float4*>(bias + j0 + tx * 8);
    float4 bb1 = *reinterpret_cast<const float4*>(bias + j0 + tx * 8 + 4);
#pragma unroll
    for (int i = 0; i < 8; ++i) {
        float4 o0 = make_float4(acc[i][0] + bb0.x, acc[i][1] + bb0.y,
                                acc[i][2] + bb0.z, acc[i][3] + bb0.w);
        float4 o1 = make_float4(acc[i][4] + bb1.x, acc[i][5] + bb1.y,
                                acc[i][6] + bb1.z, acc[i][7] + bb1.w);
        float* dst = out + (size_t)(m0 + ty * 8 + i) * 1024 + j0 + tx * 8;
        *reinterpret_cast<float4*>(dst)     = o0;
        *reinterpret_cast<float4*>(dst + 4) = o1;
    }
}

// ============================================================================
extern "C" void kernel_launch(void* const* d_in, const int* in_sizes, int n_in,
                              void* d_out, int out_size)
{
    const float* values        = (const float*)d_in[0];
    const float* keys          = (const float*)d_in[1];
    const float* query         = (const float*)d_in[2];
    const float* origin_values = (const float*)d_in[3];
    const float* origin_keys   = (const float*)d_in[4];
    const float* Wv            = (const float*)d_in[5];
    const float* Wk            = (const float*)d_in[6];
    const float* Wq            = (const float*)d_in[7];
    const float* fc_w          = (const float*)d_in[8];
    const float* fc_b          = (const float*)d_in[9];
    // d_in[10] = mask : causal-only for these shapes (HIST == L); computed analytically.
    float* out = (float*)d_out;

    const int smem_pass = (2 * 64 * PAD + 128) * (int)sizeof(float);   // 68096 B
    cudaFuncSetAttribute(pass1_kernel, cudaFuncAttributeMaxDynamicSharedMemorySize, smem_pass);
    cudaFuncSetAttribute(pass2_kernel, cudaFuncAttributeMaxDynamicSharedMemorySize, smem_pass);

    // 1) projections (5x): 65536 rows / 64 per block
    proj_kernel<<<1024, 256>>>(values,        Wv, 0);
    proj_kernel<<<1024, 256>>>(keys,          Wk, 1);
    proj_kernel<<<1024, 256>>>(query,         Wq, 2);
    proj_kernel<<<1024, 256>>>(origin_values, Wv, 3);
    proj_kernel<<<1024, 256>>>(origin_keys,   Wk, 4);

    // 2) diagonal (sampled) energies
    samp_kernel<<<8192, 256>>>();

    // 3) row log-sum-exp over causal energies (diag replaced)
    pass1_kernel<<<dim3(16, NHB), 256, smem_pass>>>();

    // 4) column sums of scores (strictly below diagonal)
    pass2_kernel<<<dim3(16, NHB), 256, smem_pass>>>();

    // 5) combine samp + origin attention
    combine_kernel<<<NLD / 256, 256>>>();

    // 6) final linear layer
    fc_kernel<<<dim3(8, 32), 256>>>(fc_w, fc_b, out);
}

// round 8
// speedup vs baseline: 1.3364x; 1.3364x over previous
#include <cuda_runtime.h>
#include <cuda_fp16.h>
#include <math_constants.h>

// Problem constants
#define NB   2
#define LL   2048
#define DD   1024
#define HH   16
#define DH   64
#define NHB  (NB*HH)                  // 32
#define NLD  (NB*LL*DD)               // 4194304
#define PAD  132                      // 128 + 4, k-major smem pitch (float4-aligned)

// logits = energy / sqrt(1024); base-2: exp(x/32) = exp2(x * log2(e)/32)
__device__ __constant__ float S2c = 1.44269504088896340736f / 32.0f;

typedef unsigned long long u64;
union F4U { float4 f; u64 u[2]; };

__device__ __forceinline__ u64 bcast2(float x) {
    u64 r;
    asm("mov.b64 %0, {%1, %1};" : "=l"(r) : "r"(__float_as_uint(x)));
    return r;
}
__device__ __forceinline__ void fma2(u64& d, u64 a, u64 b) {
    asm("fma.rn.f32x2 %0, %1, %2, %0;" : "+l"(d) : "l"(a), "l"(b));
}
__device__ __forceinline__ float2 unpack2(u64 v) {
    unsigned lo, hi;
    asm("mov.b64 {%0, %1}, %2;" : "=r"(lo), "=r"(hi) : "l"(v));
    return make_float2(__uint_as_float(lo), __uint_as_float(hi));
}

// ---------------- scratch (device globals; no allocations allowed) ----------------
__device__ float g_vp [NLD];   // v  = values @ Wv^T        (n,l,h,d) natural
__device__ float g_kp [NLD];   // k  = keys @ Wk^T
__device__ float g_qp [NLD];   // q  = query @ Wq^T
__device__ float g_ovp[NLD];   // ov = origin_values @ Wv^T
__device__ float g_okp[NLD];   // ok = origin_keys @ Wk^T
__device__ float g_samp  [NHB*LL];   // samp_energy[n,h,l] = q(l)·k(l)
__device__ float g_lse2  [NHB*LL];   // log2( sum_l exp2(logit2) ) per row q
__device__ float g_colsum[NHB*LL];   // sum_{q>l} scores[q,l]
__device__ float g_X  [NLD];         // attention output pre-fc
// unnormalized scores, TRANSPOSED: g_P[nh][l][q] = exp2(e[q,l]*S2), fp16.
// Only q >= ltile region is ever written/read (lower triangle).
__device__ __half g_P[(size_t)NHB * LL * LL];   // 268 MB

// ============================================================================
// 1) Projection: out[r, :] = X[r, :] @ W^T  for r in [0, N*L*H), 64x64 weight.
//    Block = 64 rows x 64 cols, 16x16 threads, 4x4 microtile, packed f32x2 FMA.
// ============================================================================
__global__ void __launch_bounds__(256)
proj_kernel(const float* __restrict__ X, const float* __restrict__ W, int which)
{
    float* dsts[5] = { g_vp, g_kp, g_qp, g_ovp, g_okp };
    float* out = dsts[which];

    __shared__ float XsT[64*68];   // k-major: XsT[i][r]
    __shared__ float WsT[64*68];   // k-major: WsT[i][j] = W[j][i]

    const int tid  = threadIdx.x;
    const int rho0 = blockIdx.x * 64;
    const float* Xb = X + (size_t)rho0 * 64;

#pragma unroll
    for (int t = 0; t < 4; ++t) {
        int fid = tid + t * 256;           // 0..1023 float4s
        int r   = fid >> 4;                // row / weight row j
        int i4  = fid & 15;                // k-group
        float4 v = *reinterpret_cast<const float4*>(Xb + fid * 4);
        float* p = XsT + (i4 * 4) * 68 + r;
        p[0] = v.x; p[68] = v.y; p[136] = v.z; p[204] = v.w;
        float4 w = *reinterpret_cast<const float4*>(W + fid * 4);
        float* pw = WsT + (i4 * 4) * 68 + r;
        pw[0] = w.x; pw[68] = w.y; pw[136] = w.z; pw[204] = w.w;
    }
    __syncthreads();

    const int ty = tid >> 4, tx = tid & 15;
    u64 acc[4][2] = {};
#pragma unroll 8
    for (int i = 0; i < 64; ++i) {
        float4 a = *reinterpret_cast<const float4*>(XsT + i * 68 + ty * 4);
        F4U bu; bu.f = *reinterpret_cast<const float4*>(WsT + i * 68 + tx * 4);
        float av[4] = {a.x, a.y, a.z, a.w};
#pragma unroll
        for (int r = 0; r < 4; ++r) {
            u64 ar = bcast2(av[r]);
            fma2(acc[r][0], ar, bu.u[0]);
            fma2(acc[r][1], ar, bu.u[1]);
        }
    }
#pragma unroll
    for (int r = 0; r < 4; ++r) {
        float2 p0 = unpack2(acc[r][0]);
        float2 p1 = unpack2(acc[r][1]);
        float4 o = make_float4(p0.x, p0.y, p1.x, p1.y);
        *reinterpret_cast<float4*>(out + (size_t)(rho0 + ty * 4 + r) * 64 + tx * 4) = o;
    }
}

// ============================================================================
// 2) samp_energy[n,h,l] = dot(q[n,l,h,:], k[n,l,h,:])  — one warp per row
// ============================================================================
__global__ void __launch_bounds__(256)
samp_kernel()
{
    int gw   = blockIdx.x * 8 + (threadIdx.x >> 5);   // (n*L + l)*H + h
    int lane = threadIdx.x & 31;
    int n = gw >> 15;
    int rem = gw & 32767;
    int l = rem >> 4;
    int h = rem & 15;
    size_t base = (size_t)gw * 64;
    float p = g_qp[base + lane]      * g_kp[base + lane]
            + g_qp[base + 32 + lane] * g_kp[base + 32 + lane];
#pragma unroll
    for (int o = 16; o; o >>= 1) p += __shfl_xor_sync(0xffffffffu, p, o);
    if (lane == 0) g_samp[(n * HH + h) * LL + l] = p;
}

// ---------------- shared tile loader: 128 rows x 64 cols -> k-major [64][PAD] ----
__device__ __forceinline__ void
load_tileT(const float* __restrict__ src, size_t base, int r0, float* dstT, int tid)
{
#pragma unroll
    for (int t = 0; t < 8; ++t) {
        int fid = tid + t * 256;          // 0..2047 float4s
        int m   = fid >> 4;               // row in tile 0..127
        int d4  = fid & 15;               // k group 0..15
        const float4 v = *reinterpret_cast<const float4*>(
            src + base + (size_t)(r0 + m) * DD + d4 * 4);
        float* p = dstT + (d4 * 4) * PAD + m;
        p[0] = v.x; p[PAD] = v.y; p[2*PAD] = v.z; p[3*PAD] = v.w;
    }
}

// ---------------- 8x8 microtile (f32x2 packed): acc2[i][j2] over d ----------------
__device__ __forceinline__ void
mma_tile2(u64 acc[8][4], const float* __restrict__ aT, const float* __restrict__ bT,
          int ty, int tx)
{
#pragma unroll 8
    for (int d = 0; d < 64; ++d) {
        float4 t0 = *reinterpret_cast<const float4*>(aT + d * PAD + ty * 8);
        float4 t1 = *reinterpret_cast<const float4*>(aT + d * PAD + ty * 8 + 4);
        F4U b0; b0.f = *reinterpret_cast<const float4*>(bT + d * PAD + tx * 8);
        F4U b1; b1.f = *reinterpret_cast<const float4*>(bT + d * PAD + tx * 8 + 4);
        float a[8] = {t0.x, t0.y, t0.z, t0.w, t1.x, t1.y, t1.z, t1.w};
#pragma unroll
        for (int i = 0; i < 8; ++i) {
            u64 ai = bcast2(a[i]);
            fma2(acc[i][0], ai, b0.u[0]);
            fma2(acc[i][1], ai, b0.u[1]);
            fma2(acc[i][2], ai, b1.u[0]);
            fma2(acc[i][3], ai, b1.u[1]);
        }
    }
}

// ============================================================================
// 3) Pass 1: per-row log2-sum-exp over the causal row (diag replaced by samp),
//    AND store unnormalized scores P[q,l]=exp2(e*S2) transposed into g_P[nh][l][q].
//    block = (qblk, nh); 128 rows; tiles over columns 0..q0+127.
// ============================================================================
__global__ void __launch_bounds__(256, 2)
pass1_kernel()
{
    extern __shared__ float sm[];
    float* okT   = sm;
    float* qsT   = sm + 64 * PAD;
    float* sampS = sm + 2 * 64 * PAD;   // 128 floats

    const int tid = threadIdx.x;
    const int ty = tid >> 4, tx = tid & 15;
    const int nh = blockIdx.y;
    const int n = nh >> 4, h = nh & 15;
    const int qblk = blockIdx.x;
    const int q0 = qblk * 128;
    const size_t base = (size_t)n * LL * DD + (size_t)h * DH;
    const size_t pbase = (size_t)nh * LL * LL;
    const float S2 = S2c;

    load_tileT(g_qp, base, q0, qsT, tid);
    if (tid < 128) sampS[tid] = g_samp[nh * LL + q0 + tid];

    float srun[8] = {};
    for (int ct = 0; ct <= qblk; ++ct) {
        __syncthreads();
        load_tileT(g_okp, base, ct * 128, okT, tid);
        __syncthreads();

        u64 acc[8][4] = {};
        mma_tile2(acc, qsT, okT, ty, tx);
        float accf[8][8];
#pragma unroll
        for (int i = 0; i < 8; ++i)
#pragma unroll
            for (int j2 = 0; j2 < 4; ++j2) {
                float2 p = unpack2(acc[i][j2]);
                accf[i][2*j2]   = p.x;
                accf[i][2*j2+1] = p.y;
            }

        const bool dt = (ct == qblk);
#pragma unroll
        for (int j = 0; j < 8; ++j) {
            const int cloc = tx * 8 + j;
            const int l = ct * 128 + cloc;
            float v[8];
#pragma unroll
            for (int i = 0; i < 8; ++i) v[i] = exp2f(accf[i][j] * S2);

            // store 8 consecutive-q fp16 scores (transposed layout)
            __half2 hs[4];
            hs[0] = __floats2half2_rn(v[0], v[1]);
            hs[1] = __floats2half2_rn(v[2], v[3]);
            hs[2] = __floats2half2_rn(v[4], v[5]);
            hs[3] = __floats2half2_rn(v[6], v[7]);
            *reinterpret_cast<uint4*>(g_P + pbase + (size_t)l * LL + q0 + ty * 8) =
                *reinterpret_cast<uint4*>(hs);

#pragma unroll
            for (int i = 0; i < 8; ++i) {
                const int rloc = ty * 8 + i;
                if (dt) {
                    if (cloc > rloc) continue;                        // causal
                    if (cloc == rloc) { srun[i] += exp2f(sampS[rloc] * S2); continue; }
                }
                srun[i] += v[i];
            }
        }
    }

#pragma unroll
    for (int i = 0; i < 8; ++i) {
        float s = srun[i];
        s += __shfl_xor_sync(0xffffffffu, s, 1);
        s += __shfl_xor_sync(0xffffffffu, s, 2);
        s += __shfl_xor_sync(0xffffffffu, s, 4);
        s += __shfl_xor_sync(0xffffffffu, s, 8);
        if (tx == 0) g_lse2[nh * LL + q0 + ty * 8 + i] = log2f(s);
    }
}

// ============================================================================
// 4) colsum[n,h,l] = sum_{q>l} P[q,l] * 2^(-lse2[q])  — memory-bound reduction
//    over rows of the transposed score matrix. One warp per l.
// ============================================================================
__global__ void __launch_bounds__(256)
colsum_kernel()
{
    __shared__ float w[LL];
    const int nh = blockIdx.y;
    const int tid = threadIdx.x;
    for (int i = tid; i < LL; i += 256) w[i] = exp2f(-g_lse2[nh * LL + i]);
    __syncthreads();

    const int warp = tid >> 5, lane = tid & 31;
    const int l = blockIdx.x * 8 + warp;
    const __half* row = g_P + ((size_t)nh * LL + l) * LL;

    float s = 0.0f;
    const int qb0 = ((l + 1) >> 8) << 8;   // first 256-block containing q > l
    for (int qb = qb0; qb < LL; qb += 256) {
        int q = qb + lane * 8;
        uint4 pk = *reinterpret_cast<const uint4*>(row + q);
        __half2* h = reinterpret_cast<__half2*>(&pk);
        float2 f0 = __half22float2(h[0]);
        float2 f1 = __half22float2(h[1]);
        float2 f2 = __half22float2(h[2]);
        float2 f3 = __half22float2(h[3]);
        float vv[8] = {f0.x, f0.y, f1.x, f1.y, f2.x, f2.y, f3.x, f3.y};
#pragma unroll
        for (int t = 0; t < 8; ++t)
            if (q + t > l) s += vv[t] * w[q + t];
    }
#pragma unroll
    for (int o = 16; o; o >>= 1) s += __shfl_xor_sync(0xffffffffu, s, o);
    if (lane == 0) g_colsum[nh * LL + l] = s;
}

// ============================================================================
// 5) Combine: X[n,l,h,:] = diag_score * v + colsum * ov
// ============================================================================
__global__ void __launch_bounds__(256)
combine_kernel()
{
    int idx = blockIdx.x * 256 + threadIdx.x;     // < N*L*D
    int n = idx >> 21;
    int r = idx & 2097151;
    int l = r >> 10;
    int c = r & 1023;
    int h = c >> 6;
    int si = (n * HH + h) * LL + l;
    float dg = exp2f(g_samp[si] * S2c - g_lse2[si]);
    g_X[idx] = dg * g_vp[idx] + g_colsum[si] * g_ovp[idx];
}

// ============================================================================
// 6) FC: out = X @ fc_w^T + fc_b   (4096 x 1024 x 1024, NT SGEMM, f32x2)
// ============================================================================
__global__ void __launch_bounds__(256, 2)
fc_kernel(const float* __restrict__ W, const float* __restrict__ bias,
          float* __restrict__ out)
{
    __shared__ float As[16 * PAD];
    __shared__ float Bs[16 * PAD];

    const int tid = threadIdx.x;
    const int ty = tid >> 4, tx = tid & 15;
    const int m0 = blockIdx.y * 128;
    const int j0 = blockIdx.x * 128;

    u64 acc[8][4] = {};
    for (int kc = 0; kc < 1024; kc += 16) {
        __syncthreads();
#pragma unroll
        for (int t = 0; t < 2; ++t) {
            int fid = tid + t * 256;     // 0..511 float4s
            int r = fid >> 2, k4 = fid & 3;
            float4 va = *reinterpret_cast<const float4*>(
                g_X + (size_t)(m0 + r) * 1024 + kc + k4 * 4);
            float* pa = As + (k4 * 4) * PAD + r;
            pa[0] = va.x; pa[PAD] = va.y; pa[2*PAD] = va.z; pa[3*PAD] = va.w;
            float4 vb = *reinterpret_cast<const float4*>(
                W + (size_t)(j0 + r) * 1024 + kc + k4 * 4);
            float* pb = Bs + (k4 * 4) * PAD + r;
            pb[0] = vb.x; pb[PAD] = vb.y; pb[2*PAD] = vb.z; pb[3*PAD] = vb.w;
        }
        __syncthreads();
#pragma unroll
        for (int k = 0; k < 16; ++k) {
            float4 t0 = *reinterpret_cast<const float4*>(As + k * PAD + ty * 8);
            float4 t1 = *reinterpret_cast<const float4*>(As + k * PAD + ty * 8 + 4);
            F4U b0; b0.f = *reinterpret_cast<const float4*>(Bs + k * PAD + tx * 8);
            F4U b1; b1.f = *reinterpret_cast<const float4*>(Bs + k * PAD + tx * 8 + 4);
            float a[8] = {t0.x, t0.y, t0.z, t0.w, t1.x, t1.y, t1.z, t1.w};
#pragma unroll
            for (int i = 0; i < 8; ++i) {
                u64 ai = bcast2(a[i]);
                fma2(acc[i][0], ai, b0.u[0]);
                fma2(acc[i][1], ai, b0.u[1]);
                fma2(acc[i][2], ai, b1.u[0]);
                fma2(acc[i][3], ai, b1.u[1]);
            }
        }
    }

    float4 bb0 = *reinterpret_cast<const float4*>(bias + j0 + tx * 8);
    float4 bb1 = *reinterpret_cast<const float4*>(bias + j0 + tx * 8 + 4);
#pragma unroll
    for (int i = 0; i < 8; ++i) {
        float2 p0 = unpack2(acc[i][0]);
        float2 p1 = unpack2(acc[i][1]);
        float2 p2 = unpack2(acc[i][2]);
        float2 p3 = unpack2(acc[i][3]);
        float4 o0 = make_float4(p0.x + bb0.x, p0.y + bb0.y, p1.x + bb0.z, p1.y + bb0.w);
        float4 o1 = make_float4(p2.x + bb1.x, p2.y + bb1.y, p3.x + bb1.z, p3.y + bb1.w);
        float* dst = out + (size_t)(m0 + ty * 8 + i) * 1024 + j0 + tx * 8;
        *reinterpret_cast<float4*>(dst)     = o0;
        *reinterpret_cast<float4*>(dst + 4) = o1;
    }
}

// ============================================================================
extern "C" void kernel_launch(void* const* d_in, const int* in_sizes, int n_in,
                              void* d_out, int out_size)
{
    const float* values        = (const float*)d_in[0];
    const float* keys          = (const float*)d_in[1];
    const float* query         = (const float*)d_in[2];
    const float* origin_values = (const float*)d_in[3];
    const float* origin_keys   = (const float*)d_in[4];
    const float* Wv            = (const float*)d_in[5];
    const float* Wk            = (const float*)d_in[6];
    const float* Wq            = (const float*)d_in[7];
    const float* fc_w          = (const float*)d_in[8];
    const float* fc_b          = (const float*)d_in[9];
    // d_in[10] = mask : causal-only for these shapes (HIST == L); computed analytically.
    float* out = (float*)d_out;

    const int smem_pass = (2 * 64 * PAD + 128) * (int)sizeof(float);   // 68096 B
    cudaFuncSetAttribute(pass1_kernel, cudaFuncAttributeMaxDynamicSharedMemorySize, smem_pass);

    // 1) projections (5x): 65536 rows / 64 per block
    proj_kernel<<<1024, 256>>>(values,        Wv, 0);
    proj_kernel<<<1024, 256>>>(keys,          Wk, 1);
    proj_kernel<<<1024, 256>>>(query,         Wq, 2);
    proj_kernel<<<1024, 256>>>(origin_values, Wv, 3);
    proj_kernel<<<1024, 256>>>(origin_keys,   Wk, 4);

    // 2) diagonal (sampled) energies
    samp_kernel<<<8192, 256>>>();

    // 3) row log-sum-exp over causal energies (diag replaced) + store P (fp16, transposed)
    pass1_kernel<<<dim3(16, NHB), 256, smem_pass>>>();

    // 4) weighted column sums of stored scores (strictly below diagonal)
    colsum_kernel<<<dim3(LL / 8, NHB), 256>>>();

    // 5) combine samp + origin attention
    combine_kernel<<<NLD / 256, 256>>>();

    // 6) final linear layer
    fc_kernel<<<dim3(8, 32), 256>>>(fc_w, fc_b, out);
}

// round 9
// speedup vs baseline: 3.9488x; 2.9549x over previous
#include <cuda_runtime.h>
#include <cuda_fp16.h>

// Problem constants
#define NB   2
#define LL   2048
#define DD   1024
#define HH   16
#define DH   64
#define NHB  (NB*HH)                  // 32
#define NLD  (NB*LL*DD)               // 4194304
#define KP   72                       // smem pitch in halves (144B rows: ldmatrix conflict-free)
#define QSPLIT 4

// logits = energy / sqrt(1024); base-2: exp(x/32) = exp2(x * log2(e)/32)
__device__ __constant__ float S2c = 1.44269504088896340736f / 32.0f;

// ---------------- scratch (device globals; no allocations allowed) ----------------
__device__ __half g_vh [NLD];
__device__ __half g_kh [NLD];
__device__ __half g_qh [NLD];
__device__ __half g_ovh[NLD];
__device__ __half g_okh[NLD];
__device__ __half g_fwh[DD*DD];
__device__ __half g_Xh [NLD];
__device__ float  g_samp  [NHB*LL];
__device__ float  g_lse2  [NHB*LL];
__device__ float  g_colpart[QSPLIT*NHB*LL];
// unnormalized scores, q-major: g_P[nh][q][l] = exp2(e[q,l]*S2), fp16 (lower triangle used)
__device__ __half g_P[(size_t)NHB * LL * LL];   // 268 MB

// ---------------- mma.sync helpers ----------------
__device__ __forceinline__ unsigned sptr(const void* p) {
    return (unsigned)__cvta_generic_to_shared(p);
}
__device__ __forceinline__ void ldsm4(unsigned r[4], unsigned a) {
    asm volatile("ldmatrix.sync.aligned.m8n8.x4.shared.b16 {%0,%1,%2,%3}, [%4];"
        : "=r"(r[0]), "=r"(r[1]), "=r"(r[2]), "=r"(r[3]) : "r"(a));
}
__device__ __forceinline__ void hmma(float c[4], const unsigned a[4], const unsigned b[2]) {
    asm volatile("mma.sync.aligned.m16n8k16.row.col.f32.f16.f16.f32 "
        "{%0,%1,%2,%3},{%4,%5,%6,%7},{%8,%9},{%0,%1,%2,%3};"
        : "+f"(c[0]), "+f"(c[1]), "+f"(c[2]), "+f"(c[3])
        : "r"(a[0]), "r"(a[1]), "r"(a[2]), "r"(a[3]), "r"(b[0]), "r"(b[1]));
}
__device__ __forceinline__ uint4 cvt8(float4 f0, float4 f1) {
    __half2 h[4] = { __floats2half2_rn(f0.x, f0.y), __floats2half2_rn(f0.z, f0.w),
                     __floats2half2_rn(f1.x, f1.y), __floats2half2_rn(f1.z, f1.w) };
    return *reinterpret_cast<uint4*>(h);
}

// A-operand ldmatrix address for a 16x16 tile at (row0, k0) in [.][KP] smem
__device__ __forceinline__ unsigned a_addr(unsigned base, int row0, int k0, int lane) {
    return base + (unsigned)(((row0 + (lane & 15)) * KP + k0 + ((lane >> 4) << 3)) * 2);
}
// B-operand pair: loads 2 adjacent n-tiles (16 n-rows) at (n0, k0); fills b[0..1], b[2..3]... via regs
__device__ __forceinline__ unsigned b_addr(unsigned base, int n0, int k0, int lane) {
    int g = lane & 7, sel = lane >> 3;
    return base + (unsigned)(((n0 + g + ((sel >> 1) << 3)) * KP + k0 + ((sel & 1) << 3)) * 2);
}

// ============================================================================
// 0) convert fc_w to fp16
// ============================================================================
__global__ void __launch_bounds__(256)
cvtw_kernel(const float* __restrict__ W)
{
    int u = blockIdx.x * 256 + threadIdx.x;          // 131072 units of 8
    float4 f0 = *reinterpret_cast<const float4*>(W + (size_t)u * 8);
    float4 f1 = *reinterpret_cast<const float4*>(W + (size_t)u * 8 + 4);
    *reinterpret_cast<uint4*>(g_fwh + (size_t)u * 8) = cvt8(f0, f1);
}

// ============================================================================
// 1) Fused projections: out = X @ W^T (65536 x 64 x 64), fp16 HMMA, half out.
//    grid (256, 5); block 256 rows. warps 4x2 (m64 x n32).
// ============================================================================
__global__ void __launch_bounds__(256)
proj_kernel(const float* __restrict__ v_in, const float* __restrict__ k_in,
            const float* __restrict__ q_in, const float* __restrict__ ov_in,
            const float* __restrict__ ok_in,
            const float* __restrict__ Wv, const float* __restrict__ Wk,
            const float* __restrict__ Wq)
{
    __shared__ __half As[256 * KP];
    __shared__ __half Ws[64 * KP];

    const float* X; const float* W; __half* out;
    switch (blockIdx.y) {
        case 0:  X = v_in;  W = Wv; out = g_vh;  break;
        case 1:  X = k_in;  W = Wk; out = g_kh;  break;
        case 2:  X = q_in;  W = Wq; out = g_qh;  break;
        case 3:  X = ov_in; W = Wv; out = g_ovh; break;
        default: X = ok_in; W = Wk; out = g_okh; break;
    }
    const int tid = threadIdx.x;
    const size_t r0 = (size_t)blockIdx.x * 256;
    const float* Xb = X + r0 * 64;

#pragma unroll
    for (int t = 0; t < 8; ++t) {
        int u = tid + t * 256;                 // 2048 units of 8 halves
        int m = u >> 3, d8 = u & 7;
        float4 f0 = *reinterpret_cast<const float4*>(Xb + m * 64 + d8 * 8);
        float4 f1 = *reinterpret_cast<const float4*>(Xb + m * 64 + d8 * 8 + 4);
        *reinterpret_cast<uint4*>(As + m * KP + d8 * 8) = cvt8(f0, f1);
    }
#pragma unroll
    for (int t = 0; t < 2; ++t) {
        int u = tid + t * 256;                 // 512 units
        int m = u >> 3, d8 = u & 7;
        float4 f0 = *reinterpret_cast<const float4*>(W + m * 64 + d8 * 8);
        float4 f1 = *reinterpret_cast<const float4*>(W + m * 64 + d8 * 8 + 4);
        *reinterpret_cast<uint4*>(Ws + m * KP + d8 * 8) = cvt8(f0, f1);
    }
    __syncthreads();

    const int warp = tid >> 5, lane = tid & 31;
    const int wm = warp >> 1, wn = warp & 1;   // m: 4x64, n: 2x32
    const unsigned aB = sptr(As), wB = sptr(Ws);

    float c[4][4][4] = {};
#pragma unroll
    for (int kk = 0; kk < 4; ++kk) {
        const int k0 = kk * 16;
        unsigned a[4][4], b[4][2];
#pragma unroll
        for (int mt = 0; mt < 4; ++mt)
            ldsm4(a[mt], a_addr(aB, wm * 64 + mt * 16, k0, lane));
#pragma unroll
        for (int p = 0; p < 2; ++p) {
            unsigned r[4];
            ldsm4(r, b_addr(wB, wn * 32 + p * 16, k0, lane));
            b[2*p][0] = r[0]; b[2*p][1] = r[1];
            b[2*p+1][0] = r[2]; b[2*p+1][1] = r[3];
        }
#pragma unroll
        for (int mt = 0; mt < 4; ++mt)
#pragma unroll
            for (int nt = 0; nt < 4; ++nt)
                hmma(c[mt][nt], a[mt], b[nt]);
    }

#pragma unroll
    for (int mt = 0; mt < 4; ++mt) {
        int rr = wm * 64 + mt * 16 + (lane >> 2);
#pragma unroll
        for (int nt = 0; nt < 4; ++nt) {
            int cc = wn * 32 + nt * 8 + 2 * (lane & 3);
            *reinterpret_cast<__half2*>(out + (r0 + rr) * 64 + cc) =
                __floats2half2_rn(c[mt][nt][0], c[mt][nt][1]);
            *reinterpret_cast<__half2*>(out + (r0 + rr + 8) * 64 + cc) =
                __floats2half2_rn(c[mt][nt][2], c[mt][nt][3]);
        }
    }
}

// ============================================================================
// 2) samp_energy[n,h,l] = dot(q[l], k[l]) — one warp per row, fp16 in, fp32 dot
// ============================================================================
__global__ void __launch_bounds__(256)
samp_kernel()
{
    int gw   = blockIdx.x * 8 + (threadIdx.x >> 5);   // (n*L + l)*H + h
    int lane = threadIdx.x & 31;
    int n = gw >> 15, rem = gw & 32767, l = rem >> 4, h = rem & 15;
    float2 fq = __half22float2(*reinterpret_cast<const __half2*>(g_qh + (size_t)gw * 64 + lane * 2));
    float2 fk = __half22float2(*reinterpret_cast<const __half2*>(g_kh + (size_t)gw * 64 + lane * 2));
    float p = fq.x * fk.x + fq.y * fk.y;
#pragma unroll
    for (int o = 16; o; o >>= 1) p += __shfl_xor_sync(0xffffffffu, p, o);
    if (lane == 0) g_samp[(n * HH + h) * LL + l] = p;
}

// ============================================================================
// 3) Pass 1: HMMA QK^T per (q-tile, nh); per-row sum of exp2 (diag -> samp),
//    stores P[q][l] = exp2(e*S2) as fp16 (q-major).
// ============================================================================
__global__ void __launch_bounds__(256)
pass1_kernel()
{
    __shared__ __half qs[128 * KP];
    __shared__ __half ks[128 * KP];
    __shared__ float sampS[128];
    __shared__ float rowsum[4 * 128];

    const int tid = threadIdx.x, warp = tid >> 5, lane = tid & 31;
    const int wm = warp >> 2, wn = warp & 3;          // m: 2x64, n: 4x32
    const int nh = blockIdx.y, n = nh >> 4, h = nh & 15;
    const int qblk = 15 - blockIdx.x;                 // longest blocks first
    const int q0 = qblk * 128;
    const size_t baseh = (size_t)n * LL * HH * DH + (size_t)h * DH;
    const size_t pbase = (size_t)nh * LL * LL;
    const float S2 = S2c;

    const __half* qsrc = g_qh + baseh;
#pragma unroll
    for (int t = 0; t < 4; ++t) {
        int u = tid + t * 256;                        // 1024 units of 8 halves
        int m = u >> 3, d8 = u & 7;
        *reinterpret_cast<uint4*>(qs + m * KP + d8 * 8) =
            *reinterpret_cast<const uint4*>(qsrc + (size_t)(q0 + m) * (HH * DH) + d8 * 8);
    }
    if (tid < 128) sampS[tid] = g_samp[nh * LL + q0 + tid];

    const unsigned qB = sptr(qs), kB = sptr(ks);
    float srun[4][2] = {};                            // [mt][row-half]

    for (int ct = 0; ct <= qblk; ++ct) {
        __syncthreads();
#pragma unroll
        for (int t = 0; t < 4; ++t) {
            int u = tid + t * 256;
            int m = u >> 3, d8 = u & 7;
            *reinterpret_cast<uint4*>(ks + m * KP + d8 * 8) =
                *reinterpret_cast<const uint4*>(g_okh + baseh +
                    (size_t)(ct * 128 + m) * (HH * DH) + d8 * 8);
        }
        __syncthreads();

        float c[4][4][4] = {};
#pragma unroll
        for (int kk = 0; kk < 4; ++kk) {
            const int k0 = kk * 16;
            unsigned a[4][4], b[4][2];
#pragma unroll
            for (int mt = 0; mt < 4; ++mt)
                ldsm4(a[mt], a_addr(qB, wm * 64 + mt * 16, k0, lane));
#pragma unroll
            for (int p = 0; p < 2; ++p) {
                unsigned r[4];
                ldsm4(r, b_addr(kB, wn * 32 + p * 16, k0, lane));
                b[2*p][0] = r[0]; b[2*p][1] = r[1];
                b[2*p+1][0] = r[2]; b[2*p+1][1] = r[3];
            }
#pragma unroll
            for (int mt = 0; mt < 4; ++mt)
#pragma unroll
                for (int nt = 0; nt < 4; ++nt)
                    hmma(c[mt][nt], a[mt], b[nt]);
        }

        const bool dt = (ct == qblk);
        const int l0 = ct * 128;
#pragma unroll
        for (int mt = 0; mt < 4; ++mt) {
            const int rA = wm * 64 + mt * 16 + (lane >> 2);   // local q row (c0,c1)
            const int rB = rA + 8;                            // local q row (c2,c3)
#pragma unroll
            for (int nt = 0; nt < 4; ++nt) {
                const int cl = wn * 32 + nt * 8 + 2 * (lane & 3);   // local l col
                float p0 = exp2f(c[mt][nt][0] * S2);
                float p1 = exp2f(c[mt][nt][1] * S2);
                float p2 = exp2f(c[mt][nt][2] * S2);
                float p3 = exp2f(c[mt][nt][3] * S2);
                *reinterpret_cast<__half2*>(g_P + pbase + (size_t)(q0 + rA) * LL + l0 + cl) =
                    __floats2half2_rn(p0, p1);
                *reinterpret_cast<__half2*>(g_P + pbase + (size_t)(q0 + rB) * LL + l0 + cl) =
                    __floats2half2_rn(p2, p3);
                if (dt) {
                    if (cl     < rA) srun[mt][0] += p0;
                    else if (cl     == rA) srun[mt][0] += exp2f(sampS[rA] * S2);
                    if (cl + 1 < rA) srun[mt][0] += p1;
                    else if (cl + 1 == rA) srun[mt][0] += exp2f(sampS[rA] * S2);
                    if (cl     < rB) srun[mt][1] += p2;
                    else if (cl     == rB) srun[mt][1] += exp2f(sampS[rB] * S2);
                    if (cl + 1 < rB) srun[mt][1] += p3;
                    else if (cl + 1 == rB) srun[mt][1] += exp2f(sampS[rB] * S2);
                } else {
                    srun[mt][0] += p0 + p1;
                    srun[mt][1] += p2 + p3;
                }
            }
        }
    }

    // deterministic block reduction: lane-quad reduce, per-wn smem slot, final sum
#pragma unroll
    for (int mt = 0; mt < 4; ++mt)
#pragma unroll
        for (int hf = 0; hf < 2; ++hf) {
            float s = srun[mt][hf];
            s += __shfl_xor_sync(0xffffffffu, s, 1);
            s += __shfl_xor_sync(0xffffffffu, s, 2);
            if ((lane & 3) == 0)
                rowsum[wn * 128 + wm * 64 + mt * 16 + (lane >> 2) + hf * 8] = s;
        }
    __syncthreads();
    if (tid < 128) {
        float s = rowsum[tid] + rowsum[128 + tid] + rowsum[256 + tid] + rowsum[384 + tid];
        g_lse2[nh * LL + q0 + tid] = log2f(s);
    }
}

// ============================================================================
// 4) colsum partials: colpart[part][nh][l] = sum_{q in slice, q>l} P[q][l]*2^-lse2[q]
//    grid (LL/512, NHB, QSPLIT); thread owns 2 adjacent l, coalesced row sweep.
// ============================================================================
__global__ void __launch_bounds__(256)
colsum_kernel()
{
    __shared__ float w[LL];
    const int nh = blockIdx.y, tid = threadIdx.x;
    for (int i = tid; i < LL; i += 256) w[i] = exp2f(-g_lse2[nh * LL + i]);
    __syncthreads();

    const int l0 = blockIdx.x * 512;
    const int l = l0 + tid * 2;
    const int part = blockIdx.z;
    const int span = LL - l0;
    int qa = l0 + (span * part) / QSPLIT;
    int qb = l0 + (span * (part + 1)) / QSPLIT;
    if (qa < l0 + 1) qa = l0 + 1;

    const __half* base = g_P + (size_t)nh * LL * LL;
    float s0 = 0.0f, s1 = 0.0f;
#pragma unroll 8
    for (int q = qa; q < qb; ++q) {
        float2 f = __half22float2(*reinterpret_cast<const __half2*>(base + (size_t)q * LL + l));
        float wq = w[q];
        if (q > l)     s0 += f.x * wq;
        if (q > l + 1) s1 += f.y * wq;
    }
    float* dst = g_colpart + ((size_t)part * NHB + nh) * LL;
    dst[l]     = s0;
    dst[l + 1] = s1;
}

// ============================================================================
// 5) Combine: X[n,l,h,:] = diag_score * v + colsum * ov   (half in/out)
// ============================================================================
__global__ void __launch_bounds__(256)
combine_kernel()
{
    int u = blockIdx.x * 256 + threadIdx.x;          // unit of 8 halves; NLD/8 units
    int hidx = u >> 3;                                // (n*LL + l)*HH + h
    int h = hidx & 15;
    int nl = hidx >> 4;
    int l = nl & (LL - 1);
    int n = nl >> 11;
    int si = (n * HH + h) * LL + l;
    float dg = exp2f(g_samp[si] * S2c - g_lse2[si]);
    float cs = g_colpart[si] + g_colpart[NHB * LL + si]
             + g_colpart[2 * NHB * LL + si] + g_colpart[3 * NHB * LL + si];

    uint4 v4 = *reinterpret_cast<const uint4*>(g_vh  + (size_t)u * 8);
    uint4 o4 = *reinterpret_cast<const uint4*>(g_ovh + (size_t)u * 8);
    __half2* vh = reinterpret_cast<__half2*>(&v4);
    __half2* oh = reinterpret_cast<__half2*>(&o4);
    __half2 r[4];
#pragma unroll
    for (int i = 0; i < 4; ++i) {
        float2 fv = __half22float2(vh[i]);
        float2 fo = __half22float2(oh[i]);
        r[i] = __floats2half2_rn(dg * fv.x + cs * fo.x, dg * fv.y + cs * fo.y);
    }
    *reinterpret_cast<uint4*>(g_Xh + (size_t)u * 8) = *reinterpret_cast<uint4*>(r);
}

// ============================================================================
// 6) FC: out = X @ fc_w^T + fc_b  (4096 x 1024 x 1024), fp16 HMMA, fp32 out
// ============================================================================
__global__ void __launch_bounds__(256)
fc_kernel(const float* __restrict__ bias, float* __restrict__ out)
{
    __shared__ __half As[128 * KP];
    __shared__ __half Bs[128 * KP];

    const int tid = threadIdx.x, warp = tid >> 5, lane = tid & 31;
    const int wm = warp >> 2, wn = warp & 3;          // m: 2x64, n: 4x32
    const int m0 = blockIdx.y * 128, j0 = blockIdx.x * 128;
    const unsigned aB = sptr(As), bB = sptr(Bs);

    float c[4][4][4] = {};
    for (int kc = 0; kc < 1024; kc += 64) {
        __syncthreads();
#pragma unroll
        for (int t = 0; t < 4; ++t) {
            int u = tid + t * 256;                    // 1024 units of 8 halves
            int m = u >> 3, d8 = u & 7;
            *reinterpret_cast<uint4*>(As + m * KP + d8 * 8) =
                *reinterpret_cast<const uint4*>(g_Xh + (size_t)(m0 + m) * 1024 + kc + d8 * 8);
            *reinterpret_cast<uint4*>(Bs + m * KP + d8 * 8) =
                *reinterpret_cast<const uint4*>(g_fwh + (size_t)(j0 + m) * 1024 + kc + d8 * 8);
        }
        __syncthreads();
#pragma unroll
        for (int kk = 0; kk < 4; ++kk) {
            const int k0 = kk * 16;
            unsigned a[4][4], b[4][2];
#pragma unroll
            for (int mt = 0; mt < 4; ++mt)
                ldsm4(a[mt], a_addr(aB, wm * 64 + mt * 16, k0, lane));
#pragma unroll
            for (int p = 0; p < 2; ++p) {
                unsigned r[4];
                ldsm4(r, b_addr(bB, wn * 32 + p * 16, k0, lane));
                b[2*p][0] = r[0]; b[2*p][1] = r[1];
                b[2*p+1][0] = r[2]; b[2*p+1][1] = r[3];
            }
#pragma unroll
            for (int mt = 0; mt < 4; ++mt)
#pragma unroll
                for (int nt = 0; nt < 4; ++nt)
                    hmma(c[mt][nt], a[mt], b[nt]);
        }
    }

#pragma unroll
    for (int mt = 0; mt < 4; ++mt) {
        int rr = m0 + wm * 64 + mt * 16 + (lane >> 2);
#pragma unroll
        for (int nt = 0; nt < 4; ++nt) {
            int cc = j0 + wn * 32 + nt * 8 + 2 * (lane & 3);
            float2 bb = *reinterpret_cast<const float2*>(bias + cc);
            *reinterpret_cast<float2*>(out + (size_t)rr * 1024 + cc) =
                make_float2(c[mt][nt][0] + bb.x, c[mt][nt][1] + bb.y);
            *reinterpret_cast<float2*>(out + (size_t)(rr + 8) * 1024 + cc) =
                make_float2(c[mt][nt][2] + bb.x, c[mt][nt][3] + bb.y);
        }
    }
}

// ============================================================================
extern "C" void kernel_launch(void* const* d_in, const int* in_sizes, int n_in,
                              void* d_out, int out_size)
{
    const float* values        = (const float*)d_in[0];
    const float* keys          = (const float*)d_in[1];
    const float* query         = (const float*)d_in[2];
    const float* origin_values = (const float*)d_in[3];
    const float* origin_keys   = (const float*)d_in[4];
    const float* Wv            = (const float*)d_in[5];
    const float* Wk            = (const float*)d_in[6];
    const float* Wq            = (const float*)d_in[7];
    const float* fc_w          = (const float*)d_in[8];
    const float* fc_b          = (const float*)d_in[9];
    // d_in[10] = mask : causal-only for these shapes (HIST == L); computed analytically.
    float* out = (float*)d_out;

    // 0) fc_w -> fp16
    cvtw_kernel<<<512, 256>>>(fc_w);

    // 1) fused projections (all 5, fp16 HMMA)
    proj_kernel<<<dim3(256, 5), 256>>>(values, keys, query, origin_values, origin_keys,
                                       Wv, Wk, Wq);

    // 2) diagonal (sampled) energies
    samp_kernel<<<8192, 256>>>();

    // 3) row log2-sum-exp (diag replaced) + store P (fp16, q-major)
    pass1_kernel<<<dim3(16, NHB), 256>>>();

    // 4) weighted column-sum partials of stored scores (strictly below diagonal)
    colsum_kernel<<<dim3(LL / 512, NHB, QSPLIT), 256>>>();

    // 5) combine samp + origin attention -> X (fp16)
    combine_kernel<<<NLD / 8 / 256, 256>>>();

    // 6) final linear layer (fp16 HMMA, fp32 out)
    fc_kernel<<<dim3(8, 32), 256>>>(fc_b, out);
}